// round 1
// baseline (speedup 1.0000x reference)
#include <cuda_runtime.h>
#include <math.h>

#define T_ 30
#define C_ 512
#define N_ 784
#define K_ 64
#define KD_ (K_ * C_)   // 32768

// ---------------- device scratch (no allocs allowed) ----------------
__device__ float g_wT[C_ * K_];            // conv_w transposed: [c][k]
__device__ float g_aT[T_ * N_ * K_];       // a' = softmax * invn, layout [t][n][k]  (~6 MB)
__device__ float g_asum[T_ * K_];          // sum_n a[t,k,n]
__device__ float g_vlad[T_ * K_ * C_];     // [t][k][c]  (~4 MB)
__device__ float g_gss[T_];                // global sumsq per t

// ---------------- pass 0: transpose W, zero accumulators ----------------
__global__ void prep_kernel(const float* __restrict__ w) {
    int i = blockIdx.x * 256 + threadIdx.x;
    if (i < C_ * K_) {
        int k = i / C_, c = i % C_;
        g_wT[c * K_ + k] = w[i];
    }
    if (i < T_ * K_) g_asum[i] = 0.f;
    if (i < T_)      g_gss[i]  = 0.f;
}

// ---------------- pass 1: invnorm + logits GEMM + softmax -> aT', asum ----------------
// grid: (ceil(N/64)=13, T), block 256
__global__ __launch_bounds__(256) void assign_kernel(
    const float* __restrict__ x, const float* __restrict__ bias)
{
    const int t   = blockIdx.y;
    const int n0  = blockIdx.x * 64;
    const int tid = threadIdx.x;
    const int ty  = tid >> 4;   // 0..15 -> k = ty*4..+3
    const int tx  = tid & 15;   // 0..15 -> n = tx*4..+3

    __shared__ float Ws[32 * 64];     // wT chunk [ci][k]
    __shared__ float Xs[32 * 64];     // x  chunk [ci][nj]
    __shared__ float Ls[64 * 64];     // logits [k][n]
    __shared__ float red[4 * 64];
    __shared__ float invn_s[64];
    __shared__ float bsm[64];
    __shared__ float rinvs[64];

    if (tid < 64) bsm[tid] = bias[tid];

    float acc[4][4];
#pragma unroll
    for (int i = 0; i < 4; i++)
#pragma unroll
        for (int j = 0; j < 4; j++) acc[i][j] = 0.f;
    float ss = 0.f;

    const float* xt = x + (size_t)t * C_ * N_;

    for (int cc = 0; cc < 16; cc++) {
#pragma unroll
        for (int j = 0; j < 8; j++) {
            int e = tid + j * 256;
            Ws[e] = g_wT[cc * 2048 + e];
        }
#pragma unroll
        for (int j = 0; j < 8; j++) {
            int e  = tid + j * 256;
            int ci = e >> 6, nj = e & 63;
            int n  = n0 + nj;
            Xs[e] = (n < N_) ? xt[(size_t)(cc * 32 + ci) * N_ + n] : 0.f;
        }
        __syncthreads();

        if (tid < 64) {  // per-column sumsq accumulation (for invn)
#pragma unroll
            for (int ci = 0; ci < 32; ci++) {
                float v = Xs[ci * 64 + tid];
                ss += v * v;
            }
        }
#pragma unroll
        for (int ci = 0; ci < 32; ci++) {
            float4 wv = *(const float4*)&Ws[ci * 64 + ty * 4];
            float4 xv = *(const float4*)&Xs[ci * 64 + tx * 4];
            acc[0][0] += wv.x * xv.x; acc[0][1] += wv.x * xv.y; acc[0][2] += wv.x * xv.z; acc[0][3] += wv.x * xv.w;
            acc[1][0] += wv.y * xv.x; acc[1][1] += wv.y * xv.y; acc[1][2] += wv.y * xv.z; acc[1][3] += wv.y * xv.w;
            acc[2][0] += wv.z * xv.x; acc[2][1] += wv.z * xv.y; acc[2][2] += wv.z * xv.z; acc[2][3] += wv.z * xv.w;
            acc[3][0] += wv.w * xv.x; acc[3][1] += wv.w * xv.y; acc[3][2] += wv.w * xv.z; acc[3][3] += wv.w * xv.w;
        }
        __syncthreads();
    }

    if (tid < 64) {
        invn_s[tid] = 1.f / fmaxf(sqrtf(ss), 1e-12f);
    }
    __syncthreads();

    // logits = acc * invn[n] + b[k] -> Ls
#pragma unroll
    for (int i = 0; i < 4; i++) {
        int k = ty * 4 + i;
        float b = bsm[k];
#pragma unroll
        for (int j = 0; j < 4; j++) {
            int n = tx * 4 + j;
            Ls[k * 64 + n] = acc[i][j] * invn_s[n] + b;
        }
    }
    __syncthreads();

    // softmax over k (64) per column; 4 threads per column, 16 rows each
    const int col = tid & 63, part = tid >> 6;
    float m = -1e30f;
#pragma unroll
    for (int kk = 0; kk < 16; kk++) m = fmaxf(m, Ls[(part * 16 + kk) * 64 + col]);
    red[part * 64 + col] = m;
    __syncthreads();
    m = fmaxf(fmaxf(red[col], red[64 + col]), fmaxf(red[128 + col], red[192 + col]));
    __syncthreads();
    float s = 0.f;
#pragma unroll
    for (int kk = 0; kk < 16; kk++) {
        float e = __expf(Ls[(part * 16 + kk) * 64 + col] - m);
        Ls[(part * 16 + kk) * 64 + col] = e;
        s += e;
    }
    red[part * 64 + col] = s;
    __syncthreads();
    float S    = red[col] + red[64 + col] + red[128 + col] + red[192 + col];
    float rinv = 1.f / S;
    if (part == 0) rinvs[col] = rinv;
    __syncthreads();

    // write aT' = a * invn  (layout [t][n][k])
    const int n = n0 + col;
    if (n < N_) {
        float  sc  = rinv * invn_s[col];
        float* dst = &g_aT[((size_t)t * N_ + n) * K_ + part * 16];
#pragma unroll
        for (int kk = 0; kk < 16; kk++)
            dst[kk] = Ls[(part * 16 + kk) * 64 + col] * sc;
    }

    // partial asum per k over this block's valid columns
    const int ncols = min(64, N_ - n0);
    if (tid < 64) {
        float as = 0.f;
        for (int c2 = 0; c2 < ncols; c2++)
            as += Ls[tid * 64 + c2] * rinvs[c2];
        atomicAdd(&g_asum[t * K_ + tid], as);
    }
}

// ---------------- pass 2: VLAD GEMM: vlad[k][c] = sum_n a'[n][k]*x[c][n] - asum[k]*cent[k][c] ----------------
// grid: (C/64=8, T), block 256
__global__ __launch_bounds__(256) void vlad_kernel(
    const float* __restrict__ x, const float* __restrict__ cent)
{
    const int t   = blockIdx.y;
    const int c0  = blockIdx.x * 64;
    const int tid = threadIdx.x;
    const int ty  = tid >> 4;
    const int tx  = tid & 15;

    __shared__ float As[32 * 64];    // [nn][k]
    __shared__ float XsT[32 * 68];   // [nn][ci] (pad 68 keeps float4 align, limits conflicts)
    __shared__ float asums[64];

    if (tid < 64) asums[tid] = g_asum[t * 64 + tid];

    float acc[4][4];
#pragma unroll
    for (int i = 0; i < 4; i++)
#pragma unroll
        for (int j = 0; j < 4; j++) acc[i][j] = 0.f;

    const float* xt  = x + (size_t)t * C_ * N_;
    const float* aTt = g_aT + (size_t)t * N_ * K_;

    for (int nc = 0; nc < 25; nc++) {
        const int n0 = nc * 32;
#pragma unroll
        for (int j = 0; j < 8; j++) {
            int e  = tid + j * 256;
            int nn = e >> 6, k = e & 63;
            As[e] = (n0 + nn < N_) ? aTt[(size_t)(n0 + nn) * K_ + k] : 0.f;
        }
#pragma unroll
        for (int j = 0; j < 8; j++) {
            int e  = tid + j * 256;
            int ci = e >> 5, nn = e & 31;
            float v = (n0 + nn < N_) ? xt[(size_t)(c0 + ci) * N_ + n0 + nn] : 0.f;
            XsT[nn * 68 + ci] = v;
        }
        __syncthreads();
#pragma unroll
        for (int nn = 0; nn < 32; nn++) {
            float4 av = *(const float4*)&As[nn * 64 + ty * 4];
            float4 xv = *(const float4*)&XsT[nn * 68 + tx * 4];
            acc[0][0] += av.x * xv.x; acc[0][1] += av.x * xv.y; acc[0][2] += av.x * xv.z; acc[0][3] += av.x * xv.w;
            acc[1][0] += av.y * xv.x; acc[1][1] += av.y * xv.y; acc[1][2] += av.y * xv.z; acc[1][3] += av.y * xv.w;
            acc[2][0] += av.z * xv.x; acc[2][1] += av.z * xv.y; acc[2][2] += av.z * xv.z; acc[2][3] += av.z * xv.w;
            acc[3][0] += av.w * xv.x; acc[3][1] += av.w * xv.y; acc[3][2] += av.w * xv.z; acc[3][3] += av.w * xv.w;
        }
        __syncthreads();
    }

#pragma unroll
    for (int i = 0; i < 4; i++) {
        int   k  = ty * 4 + i;
        float as = asums[k];
#pragma unroll
        for (int j = 0; j < 4; j++) {
            int c = c0 + tx * 4 + j;
            g_vlad[((size_t)t * K_ + k) * C_ + c] = acc[i][j] - as * cent[k * C_ + c];
        }
    }
}

// ---------------- pass 3: intra-normalization over c per (t,k), accumulate global sumsq ----------------
// grid: (K, T), block 128
__global__ __launch_bounds__(128) void intranorm_kernel() {
    const int t = blockIdx.y, k = blockIdx.x;
    const int tid = threadIdx.x;
    float* v = &g_vlad[((size_t)t * K_ + k) * C_];
    float4 val = ((float4*)v)[tid];
    float ss = val.x * val.x + val.y * val.y + val.z * val.z + val.w * val.w;
#pragma unroll
    for (int o = 16; o; o >>= 1) ss += __shfl_xor_sync(0xffffffff, ss, o);
    __shared__ float wss[4];
    if ((tid & 31) == 0) wss[tid >> 5] = ss;
    __syncthreads();
    float tot = wss[0] + wss[1] + wss[2] + wss[3];
    float sc  = 1.f / fmaxf(sqrtf(tot), 1e-12f);
    val.x *= sc; val.y *= sc; val.z *= sc; val.w *= sc;
    ((float4*)v)[tid] = val;
    if (tid == 0) atomicAdd(&g_gss[t], tot * sc * sc);
}

// ---------------- pass 4: global normalize + sum over t ----------------
// grid: KD/256 = 128, block 256
__global__ __launch_bounds__(256) void finalize_kernel(float* __restrict__ out) {
    __shared__ float gsc[T_];
    const int tid = threadIdx.x;
    if (tid < T_) gsc[tid] = 1.f / fmaxf(sqrtf(g_gss[tid]), 1e-12f);
    __syncthreads();
    const int i = blockIdx.x * 256 + tid;
    float s = 0.f;
    for (int t = 0; t < T_; t++)
        s += g_vlad[(size_t)t * KD_ + i] * gsc[t];
    out[i] = s;
}

// ---------------- launch ----------------
extern "C" void kernel_launch(void* const* d_in, const int* in_sizes, int n_in,
                              void* d_out, int out_size) {
    const float* x1     = (const float*)d_in[0];   // [30,512,28,28]
    const float* cent   = (const float*)d_in[1];   // [64,512]
    const float* conv_w = (const float*)d_in[2];   // [64,512]
    const float* conv_b = (const float*)d_in[3];   // [64]
    float* out = (float*)d_out;                    // [1, 32768]

    prep_kernel<<<128, 256>>>(conv_w);
    {
        dim3 g((N_ + 63) / 64, T_);
        assign_kernel<<<g, 256>>>(x1, conv_b);
    }
    {
        dim3 g(C_ / 64, T_);
        vlad_kernel<<<g, 256>>>(x1, cent);
    }
    {
        dim3 g(K_, T_);
        intranorm_kernel<<<g, 128>>>();
    }
    finalize_kernel<<<KD_ / 256, 256>>>(out);
}